// round 1
// baseline (speedup 1.0000x reference)
#include <cuda_runtime.h>
#include <math.h>

#define B_ 8
#define N_ 1024
#define M_ 1024
#define D_ 256
#define H_ 4
#define P_ 128
#define C_ 64   // per-head dim

// -------- device scratch (allocation-free rule: __device__ globals) --------
__device__ float g_q[B_ * H_ * N_ * C_];    // (B,H,N,C)  8 MB
__device__ float g_k[B_ * H_ * M_ * C_];    // (B,H,M,C)  8 MB
__device__ float g_v[B_ * H_ * M_ * C_];    // (B,H,M,C)  8 MB
__device__ float g_sp[B_ * H_ * N_ * P_];   // (B,H,N,P) 16 MB

// ============================================================================
// Kernel 1: fused QKV projection.
//   out[b,h,l,c] = sum_d X[b,l,d] * W[h*C+c, d] + bias[h*C+c]
// blockIdx.z selects q/k/v. 64x64 tile, K=256 in 16-chunks.
// ============================================================================
__global__ __launch_bounds__(256) void proj_kernel(
    const float* __restrict__ Xq, const float* __restrict__ Xk,
    const float* __restrict__ Xv,
    const float* __restrict__ Wq, const float* __restrict__ bq,
    const float* __restrict__ Wk, const float* __restrict__ bk,
    const float* __restrict__ Wv, const float* __restrict__ bv)
{
    const int which = blockIdx.z;
    const float* X    = (which == 0) ? Xq : (which == 1) ? Xk : Xv;
    const float* W    = (which == 0) ? Wq : (which == 1) ? Wk : Wv;
    const float* bias = (which == 0) ? bq : (which == 1) ? bk : bv;
    float* out        = (which == 0) ? g_q : (which == 1) ? g_k : g_v;

    const int r0 = blockIdx.x * 64;   // row tile (over B*L = 8192)
    const int j0 = blockIdx.y * 64;   // col tile (over D = 256)

    __shared__ float As[16][68];  // [k][row]
    __shared__ float Bs[16][68];  // [k][col]

    const int tid = threadIdx.x;
    const int tx = tid & 15, ty = tid >> 4;
    const int lr  = tid >> 2;        // 0..63
    const int lk4 = (tid & 3) * 4;   // 0,4,8,12

    float acc[4][4] = {};

    for (int kc = 0; kc < 256; kc += 16) {
        float4 a = *(const float4*)&X[(size_t)(r0 + lr) * 256 + kc + lk4];
        float4 b = *(const float4*)&W[(size_t)(j0 + lr) * 256 + kc + lk4];
        As[lk4 + 0][lr] = a.x; As[lk4 + 1][lr] = a.y;
        As[lk4 + 2][lr] = a.z; As[lk4 + 3][lr] = a.w;
        Bs[lk4 + 0][lr] = b.x; Bs[lk4 + 1][lr] = b.y;
        Bs[lk4 + 2][lr] = b.z; Bs[lk4 + 3][lr] = b.w;
        __syncthreads();
#pragma unroll
        for (int kk = 0; kk < 16; kk++) {
            float av[4], bv4[4];
#pragma unroll
            for (int i = 0; i < 4; i++) av[i]  = As[kk][ty * 4 + i];
#pragma unroll
            for (int j = 0; j < 4; j++) bv4[j] = Bs[kk][tx * 4 + j];
#pragma unroll
            for (int i = 0; i < 4; i++)
#pragma unroll
                for (int j = 0; j < 4; j++)
                    acc[i][j] = fmaf(av[i], bv4[j], acc[i][j]);
        }
        __syncthreads();
    }

#pragma unroll
    for (int j = 0; j < 4; j++) {
        const int col = j0 + tx * 4 + j;
        const float bj = bias[col];
        const int h = col >> 6, c = col & 63;
#pragma unroll
        for (int i = 0; i < 4; i++) {
            const int r = r0 + ty * 4 + i;
            const int b = r >> 10, l = r & 1023;
            out[(((size_t)(b * H_ + h) * N_) + l) * C_ + c] = acc[i][j] + bj;
        }
    }
}

// ============================================================================
// Kernel 2: scores_p_all.  sp[b,h,n,p] = sum_c q[b,h,n,c] * emb[p, h*C + c]
// Per (b,h): GEMM (N=1024, P=128, K=64).
// ============================================================================
__global__ __launch_bounds__(256) void sp_kernel(const float* __restrict__ emb)
{
    const int bh = blockIdx.z;
    const int h  = bh & (H_ - 1);
    const int n0 = blockIdx.y * 64;
    const int p0 = blockIdx.x * 64;

    __shared__ float As[16][68];  // [k][n]
    __shared__ float Bs[16][68];  // [k][p]

    const int tid = threadIdx.x;
    const int tx = tid & 15, ty = tid >> 4;
    const int lr  = tid >> 2;
    const int lk4 = (tid & 3) * 4;

    const float* qb = g_q + (size_t)bh * N_ * C_;
    float acc[4][4] = {};

    for (int kc = 0; kc < 64; kc += 16) {
        float4 a = *(const float4*)&qb[(size_t)(n0 + lr) * C_ + kc + lk4];
        float4 b = *(const float4*)&emb[(size_t)(p0 + lr) * D_ + h * C_ + kc + lk4];
        As[lk4 + 0][lr] = a.x; As[lk4 + 1][lr] = a.y;
        As[lk4 + 2][lr] = a.z; As[lk4 + 3][lr] = a.w;
        Bs[lk4 + 0][lr] = b.x; Bs[lk4 + 1][lr] = b.y;
        Bs[lk4 + 2][lr] = b.z; Bs[lk4 + 3][lr] = b.w;
        __syncthreads();
#pragma unroll
        for (int kk = 0; kk < 16; kk++) {
            float av[4], bv4[4];
#pragma unroll
            for (int i = 0; i < 4; i++) av[i]  = As[kk][ty * 4 + i];
#pragma unroll
            for (int j = 0; j < 4; j++) bv4[j] = Bs[kk][tx * 4 + j];
#pragma unroll
            for (int i = 0; i < 4; i++)
#pragma unroll
                for (int j = 0; j < 4; j++)
                    acc[i][j] = fmaf(av[i], bv4[j], acc[i][j]);
        }
        __syncthreads();
    }

    float* spb = g_sp + (size_t)bh * N_ * P_;
#pragma unroll
    for (int i = 0; i < 4; i++)
#pragma unroll
        for (int j = 0; j < 4; j++)
            spb[(size_t)(n0 + ty * 4 + i) * P_ + p0 + tx * 4 + j] = acc[i][j];
}

// ============================================================================
// Kernel 3: scores.
//   s[b,h,n,m] = factor[b,n,m] * (q.k + sp[b,h,n, idx[b,n,m]]) / 8, masked.
// Per (b,h): GEMM (N, M, K=64) with fused SMEM gather epilogue.
// Writes raw scores into attn output region.
// ============================================================================
__global__ __launch_bounds__(256) void scores_kernel(
    const float* __restrict__ factor, const int* __restrict__ eidx,
    const unsigned char* __restrict__ kmask, float* __restrict__ attn)
{
    const int bh = blockIdx.z;
    const int b  = bh >> 2;   // /H_
    const int n0 = blockIdx.y * 64;
    const int m0 = blockIdx.x * 64;

    __shared__ float Qs[16][68];
    __shared__ float Ks[16][68];
    __shared__ float Sp[64][P_];   // 32 KB: sp rows for this n-tile

    const int tid = threadIdx.x;
    const int tx = tid & 15, ty = tid >> 4;
    const int lr  = tid >> 2;
    const int lk4 = (tid & 3) * 4;

    // stage sp tile: 64 rows x 128 floats
    {
        const float* spb = g_sp + ((size_t)bh * N_ + n0) * P_;
#pragma unroll
        for (int t = tid; t < 64 * 32; t += 256) {
            const int row = t >> 5, q4 = (t & 31) * 4;
            float4 v = *(const float4*)&spb[(size_t)row * P_ + q4];
            Sp[row][q4 + 0] = v.x; Sp[row][q4 + 1] = v.y;
            Sp[row][q4 + 2] = v.z; Sp[row][q4 + 3] = v.w;
        }
    }

    const float* qb = g_q + (size_t)bh * N_ * C_;
    const float* kb = g_k + (size_t)bh * M_ * C_;
    float acc[4][4] = {};

    for (int kc = 0; kc < 64; kc += 16) {
        float4 a = *(const float4*)&qb[(size_t)(n0 + lr) * C_ + kc + lk4];
        float4 c = *(const float4*)&kb[(size_t)(m0 + lr) * C_ + kc + lk4];
        Qs[lk4 + 0][lr] = a.x; Qs[lk4 + 1][lr] = a.y;
        Qs[lk4 + 2][lr] = a.z; Qs[lk4 + 3][lr] = a.w;
        Ks[lk4 + 0][lr] = c.x; Ks[lk4 + 1][lr] = c.y;
        Ks[lk4 + 2][lr] = c.z; Ks[lk4 + 3][lr] = c.w;
        __syncthreads();
#pragma unroll
        for (int kk = 0; kk < 16; kk++) {
            float av[4], bv4[4];
#pragma unroll
            for (int i = 0; i < 4; i++) av[i]  = Qs[kk][ty * 4 + i];
#pragma unroll
            for (int j = 0; j < 4; j++) bv4[j] = Ks[kk][tx * 4 + j];
#pragma unroll
            for (int i = 0; i < 4; i++)
#pragma unroll
                for (int j = 0; j < 4; j++)
                    acc[i][j] = fmaf(av[i], bv4[j], acc[i][j]);
        }
        __syncthreads();
    }

#pragma unroll
    for (int i = 0; i < 4; i++) {
        const int n = n0 + ty * 4 + i;
        const size_t fbase = ((size_t)b * N_ + n) * M_ + m0;
        float* orow = attn + ((size_t)bh * N_ + n) * M_ + m0;
#pragma unroll
        for (int j = 0; j < 4; j++) {
            const int m = tx * 4 + j;
            const int id = eidx[fbase + m];
            float s = factor[fbase + m] * (acc[i][j] + Sp[ty * 4 + i][id]) * 0.125f;
            if (kmask[b * M_ + m0 + m]) s = -INFINITY;
            orow[m] = s;
        }
    }
}

// ============================================================================
// Kernel 4: row softmax in-place over attn (B*H*N rows of M=1024).
// ============================================================================
__global__ __launch_bounds__(256) void softmax_kernel(float* __restrict__ attn)
{
    __shared__ float red[256];
    const int tid = threadIdx.x;
    float* row = attn + (size_t)blockIdx.x * M_;

    float4 v = ((float4*)row)[tid];
    float mx = fmaxf(fmaxf(v.x, v.y), fmaxf(v.z, v.w));
    red[tid] = mx; __syncthreads();
#pragma unroll
    for (int s = 128; s > 0; s >>= 1) {
        if (tid < s) red[tid] = fmaxf(red[tid], red[tid + s]);
        __syncthreads();
    }
    mx = red[0]; __syncthreads();

    v.x = expf(v.x - mx); v.y = expf(v.y - mx);
    v.z = expf(v.z - mx); v.w = expf(v.w - mx);
    float sm = v.x + v.y + v.z + v.w;
    red[tid] = sm; __syncthreads();
#pragma unroll
    for (int s = 128; s > 0; s >>= 1) {
        if (tid < s) red[tid] += red[tid + s];
        __syncthreads();
    }
    const float inv = 1.0f / red[0];
    v.x *= inv; v.y *= inv; v.z *= inv; v.w *= inv;
    ((float4*)row)[tid] = v;
}

// ============================================================================
// Kernel 5: hidden = attn @ v.  Per (b,h): GEMM (N, C=64, K=M=1024).
// Writes hidden[b,n, h*C+c].
// ============================================================================
__global__ __launch_bounds__(256) void av_kernel(
    const float* __restrict__ attn, float* __restrict__ hidden)
{
    const int bh = blockIdx.y;
    const int b  = bh >> 2;
    const int h  = bh & (H_ - 1);
    const int n0 = blockIdx.x * 64;

    __shared__ float As[16][68];  // [k][n]
    __shared__ float Vs[16][68];  // [k][c]

    const int tid = threadIdx.x;
    const int tx = tid & 15, ty = tid >> 4;
    const int lr  = tid >> 2;
    const int lk4 = (tid & 3) * 4;
    const int vr = tid >> 4, vc = (tid & 15) * 4;

    const float* ab = attn + ((size_t)bh * N_ + n0) * M_;
    const float* vb = g_v + (size_t)bh * M_ * C_;
    float acc[4][4] = {};

    for (int kc = 0; kc < M_; kc += 16) {
        float4 a = *(const float4*)&ab[(size_t)lr * M_ + kc + lk4];
        As[lk4 + 0][lr] = a.x; As[lk4 + 1][lr] = a.y;
        As[lk4 + 2][lr] = a.z; As[lk4 + 3][lr] = a.w;
        float4 w = *(const float4*)&vb[(size_t)(kc + vr) * C_ + vc];
        Vs[vr][vc + 0] = w.x; Vs[vr][vc + 1] = w.y;
        Vs[vr][vc + 2] = w.z; Vs[vr][vc + 3] = w.w;
        __syncthreads();
#pragma unroll
        for (int kk = 0; kk < 16; kk++) {
            float av[4], bv4[4];
#pragma unroll
            for (int i = 0; i < 4; i++) av[i]  = As[kk][ty * 4 + i];
#pragma unroll
            for (int j = 0; j < 4; j++) bv4[j] = Vs[kk][tx * 4 + j];
#pragma unroll
            for (int i = 0; i < 4; i++)
#pragma unroll
                for (int j = 0; j < 4; j++)
                    acc[i][j] = fmaf(av[i], bv4[j], acc[i][j]);
        }
        __syncthreads();
    }

#pragma unroll
    for (int i = 0; i < 4; i++) {
        const int n = n0 + ty * 4 + i;
#pragma unroll
        for (int j = 0; j < 4; j++)
            hidden[((size_t)b * N_ + n) * D_ + h * C_ + tx * 4 + j] = acc[i][j];
    }
}

// ============================================================================
// Launch
// ============================================================================
extern "C" void kernel_launch(void* const* d_in, const int* in_sizes, int n_in,
                              void* d_out, int out_size)
{
    const float* input_q = (const float*)d_in[0];
    const float* input_k = (const float*)d_in[1];
    const float* input_v = (const float*)d_in[2];
    const float* Wq = (const float*)d_in[3];
    const float* bq = (const float*)d_in[4];
    const float* Wk = (const float*)d_in[5];
    const float* bk = (const float*)d_in[6];
    const float* Wv = (const float*)d_in[7];
    const float* bv = (const float*)d_in[8];
    const float* emb_table = (const float*)d_in[9];
    const float* factor = (const float*)d_in[10];
    const int* eidx = (const int*)d_in[11];
    const unsigned char* kmask = (const unsigned char*)d_in[12];

    float* hidden = (float*)d_out;                                   // (B,N,D)
    float* attn   = (float*)d_out + (size_t)B_ * N_ * D_;            // (B,H,N,M)

    // 1. QKV projections (z: 0=q,1=k,2=v)
    proj_kernel<<<dim3((B_ * N_) / 64, D_ / 64, 3), 256>>>(
        input_q, input_k, input_v, Wq, bq, Wk, bk, Wv, bv);

    // 2. scores_p_all
    sp_kernel<<<dim3(P_ / 64, N_ / 64, B_ * H_), 256>>>(emb_table);

    // 3. scores with fused gather/factor/scale/mask
    scores_kernel<<<dim3(M_ / 64, N_ / 64, B_ * H_), 256>>>(factor, eidx, kmask, attn);

    // 4. softmax
    softmax_kernel<<<B_ * H_ * N_, 256>>>(attn);

    // 5. attn @ v -> hidden
    av_kernel<<<dim3(N_ / 64, B_ * H_), 256>>>(attn, hidden);
}

// round 2
// speedup vs baseline: 1.0805x; 1.0805x over previous
#include <cuda_runtime.h>
#include <math.h>
#include <stdint.h>

#define B_ 8
#define N_ 1024
#define M_ 1024
#define D_ 256
#define H_ 4
#define P_ 128
#define C_ 64

// -------- device scratch (allocation-free rule) --------
__device__ float g_q[B_ * H_ * N_ * C_];    // (B,H,N,C)
__device__ float g_k[B_ * H_ * M_ * C_];    // (B,H,M,C)
__device__ float g_v[B_ * H_ * M_ * C_];    // (B,H,M,C)

// ---------------- tf32 helpers ----------------
__device__ __forceinline__ uint32_t f2tf(float x) {
    uint32_t u;
    asm("cvt.rna.tf32.f32 %0, %1;" : "=r"(u) : "f"(x));
    return u;
}

__device__ __forceinline__ void mma8(float d[4], const uint32_t a[4], const uint32_t b[2]) {
    asm volatile(
        "mma.sync.aligned.m16n8k8.row.col.f32.tf32.tf32.f32 "
        "{%0,%1,%2,%3}, {%4,%5,%6,%7}, {%8,%9}, {%0,%1,%2,%3};"
        : "+f"(d[0]), "+f"(d[1]), "+f"(d[2]), "+f"(d[3])
        : "r"(a[0]), "r"(a[1]), "r"(a[2]), "r"(a[3]), "r"(b[0]), "r"(b[1]));
}

// ---------------- smem layout (floats) ----------------
#define S_STRIDE 1036                    // 1024 + 12 pad -> conflict-free frag loads
#define S_OFF    0                       // 32 x 1036
#define QH_OFF   33152                   // 32 x 68
#define QL_OFF   35328
#define KS_STRIDE 76                     // staged K/V/emb chunk stride
#define KH_OFF   37504                   // 64 x 76
#define KL_OFF   42368
#define SP_OFF   47232                   // 32 x 128
#define SMEM_FLOATS 51328
#define SMEM_BYTES  (SMEM_FLOATS * 4)

// ============================================================================
// Kernel 1: fused QKV projection (fp32, unchanged from R1 — known correct).
// ============================================================================
__global__ __launch_bounds__(256) void proj_kernel(
    const float* __restrict__ Xq, const float* __restrict__ Xk,
    const float* __restrict__ Xv,
    const float* __restrict__ Wq, const float* __restrict__ bq,
    const float* __restrict__ Wk, const float* __restrict__ bk,
    const float* __restrict__ Wv, const float* __restrict__ bv)
{
    const int which = blockIdx.z;
    const float* X    = (which == 0) ? Xq : (which == 1) ? Xk : Xv;
    const float* W    = (which == 0) ? Wq : (which == 1) ? Wk : Wv;
    const float* bias = (which == 0) ? bq : (which == 1) ? bk : bv;
    float* out        = (which == 0) ? g_q : (which == 1) ? g_k : g_v;

    const int r0 = blockIdx.x * 64;
    const int j0 = blockIdx.y * 64;

    __shared__ float As[16][68];
    __shared__ float Bs[16][68];

    const int tid = threadIdx.x;
    const int tx = tid & 15, ty = tid >> 4;
    const int lr  = tid >> 2;
    const int lk4 = (tid & 3) * 4;

    float acc[4][4] = {};

    for (int kc = 0; kc < 256; kc += 16) {
        float4 a = *(const float4*)&X[(size_t)(r0 + lr) * 256 + kc + lk4];
        float4 b = *(const float4*)&W[(size_t)(j0 + lr) * 256 + kc + lk4];
        As[lk4 + 0][lr] = a.x; As[lk4 + 1][lr] = a.y;
        As[lk4 + 2][lr] = a.z; As[lk4 + 3][lr] = a.w;
        Bs[lk4 + 0][lr] = b.x; Bs[lk4 + 1][lr] = b.y;
        Bs[lk4 + 2][lr] = b.z; Bs[lk4 + 3][lr] = b.w;
        __syncthreads();
#pragma unroll
        for (int kk = 0; kk < 16; kk++) {
            float av[4], bv4[4];
#pragma unroll
            for (int i = 0; i < 4; i++) av[i]  = As[kk][ty * 4 + i];
#pragma unroll
            for (int j = 0; j < 4; j++) bv4[j] = Bs[kk][tx * 4 + j];
#pragma unroll
            for (int i = 0; i < 4; i++)
#pragma unroll
                for (int j = 0; j < 4; j++)
                    acc[i][j] = fmaf(av[i], bv4[j], acc[i][j]);
        }
        __syncthreads();
    }

#pragma unroll
    for (int j = 0; j < 4; j++) {
        const int col = j0 + tx * 4 + j;
        const float bj = bias[col];
        const int h = col >> 6, c = col & 63;
#pragma unroll
        for (int i = 0; i < 4; i++) {
            const int r = r0 + ty * 4 + i;
            const int b = r >> 10, l = r & 1023;
            out[(((size_t)(b * H_ + h) * N_) + l) * C_ + c] = acc[i][j] + bj;
        }
    }
}

// ============================================================================
// Kernel 2: FUSED  sp-GEMM + scores-GEMM + gather/factor/mask + softmax
//           + attn write + AV-GEMM.  One block = 32 q-rows of one (b,h).
// tf32 mma.sync; split hi/lo precision for logits, P(single)xV(split) for AV.
// ============================================================================
__global__ __launch_bounds__(256, 1) void fused_kernel(
    const float* __restrict__ emb, const float* __restrict__ factor,
    const int* __restrict__ eidx, const unsigned char* __restrict__ kmask,
    float* __restrict__ attn, float* __restrict__ hidden)
{
    extern __shared__ float sm[];
    float*    S  = sm + S_OFF;                 // 32 x 1036 fp32 scores/probs
    uint32_t* Su = (uint32_t*)(sm + S_OFF);    // same array as tf32 bits later
    uint32_t* Qh = (uint32_t*)(sm + QH_OFF);   // 32 x 68
    uint32_t* Ql = (uint32_t*)(sm + QL_OFF);
    uint32_t* Kh = (uint32_t*)(sm + KH_OFF);   // 64 x 76 (K / V / emb chunks)
    uint32_t* Kl = (uint32_t*)(sm + KL_OFF);
    float*    Sp = sm + SP_OFF;                // 32 x 128

    const int tid  = threadIdx.x;
    const int w    = tid >> 5;      // warp 0..7
    const int lane = tid & 31;
    const int gid  = lane >> 2;     // 0..7
    const int tg   = lane & 3;      // 0..3
    const int bh = blockIdx.y, b = bh >> 2, h = bh & 3;
    const int n0 = blockIdx.x * 32;

    // ---------- stage Q (32x64) hi/lo ----------
    {
        const float* src = g_q + ((size_t)bh * N_ + n0) * C_;
#pragma unroll
        for (int j = 0; j < 2; j++) {
            int id = tid + j * 256;            // float4 id, 512 total
            int r = id >> 4, c4 = (id & 15) * 4;
            float4 v = *(const float4*)(src + (size_t)r * 64 + c4);
            float vv[4] = {v.x, v.y, v.z, v.w};
#pragma unroll
            for (int e = 0; e < 4; e++) {
                uint32_t hi = f2tf(vv[e]);
                Qh[r * 68 + c4 + e] = hi;
                Ql[r * 68 + c4 + e] = f2tf(vv[e] - __uint_as_float(hi));
            }
        }
    }

    // ---------- SP: Sp(32x128) = Q · emb_h^T  (split tf32, 2 chunks) ----------
    for (int pc = 0; pc < 2; pc++) {
        __syncthreads();
        {   // stage emb chunk: rows p = pc*64 + r, cols emb[p][h*64 + c]
            const float* src = emb + (size_t)(pc * 64) * D_ + h * 64;
#pragma unroll
            for (int j = 0; j < 4; j++) {
                int id = tid + j * 256;        // 1024 float4
                int r = id >> 4, c4 = (id & 15) * 4;
                float4 v = *(const float4*)(src + (size_t)r * D_ + c4);
                float vv[4] = {v.x, v.y, v.z, v.w};
#pragma unroll
                for (int e = 0; e < 4; e++) {
                    uint32_t hi = f2tf(vv[e]);
                    Kh[r * KS_STRIDE + c4 + e] = hi;
                    Kl[r * KS_STRIDE + c4 + e] = f2tf(vv[e] - __uint_as_float(hi));
                }
            }
        }
        __syncthreads();

        float hh[2][4] = {}, hl[2][4] = {}, lh[2][4] = {};
#pragma unroll
        for (int kb = 0; kb < 8; kb++) {
            uint32_t ah[2][4], al[2][4], bhf[2], blf[2];
#pragma unroll
            for (int mt = 0; mt < 2; mt++) {
                int r0 = mt * 16 + gid, c0 = kb * 8 + tg;
                ah[mt][0] = Qh[r0 * 68 + c0];       ah[mt][1] = Qh[(r0 + 8) * 68 + c0];
                ah[mt][2] = Qh[r0 * 68 + c0 + 4];   ah[mt][3] = Qh[(r0 + 8) * 68 + c0 + 4];
                al[mt][0] = Ql[r0 * 68 + c0];       al[mt][1] = Ql[(r0 + 8) * 68 + c0];
                al[mt][2] = Ql[r0 * 68 + c0 + 4];   al[mt][3] = Ql[(r0 + 8) * 68 + c0 + 4];
            }
            int br = w * 8 + gid, bc = kb * 8 + tg;
            bhf[0] = Kh[br * KS_STRIDE + bc]; bhf[1] = Kh[br * KS_STRIDE + bc + 4];
            blf[0] = Kl[br * KS_STRIDE + bc]; blf[1] = Kl[br * KS_STRIDE + bc + 4];
#pragma unroll
            for (int mt = 0; mt < 2; mt++) {
                mma8(hh[mt], ah[mt], bhf);
                mma8(hl[mt], ah[mt], blf);
                mma8(lh[mt], al[mt], bhf);
            }
        }
#pragma unroll
        for (int mt = 0; mt < 2; mt++) {
            int row = mt * 16 + gid;
            int col = pc * 64 + w * 8 + 2 * tg;
            float2 v0 = make_float2(hh[mt][0] + hl[mt][0] + lh[mt][0],
                                    hh[mt][1] + hl[mt][1] + lh[mt][1]);
            float2 v1 = make_float2(hh[mt][2] + hl[mt][2] + lh[mt][2],
                                    hh[mt][3] + hl[mt][3] + lh[mt][3]);
            *(float2*)(Sp + row * 128 + col)       = v0;
            *(float2*)(Sp + (row + 8) * 128 + col) = v1;
        }
    }

    // ---------- GEMM1: S(32x1024) = Q · K^T (split tf32, 16 chunks) ----------
    for (int mc = 0; mc < 16; mc++) {
        __syncthreads();
        {   // stage K chunk (64 m-rows x 64 c)
            const float* src = g_k + ((size_t)bh * M_ + mc * 64) * C_;
#pragma unroll
            for (int j = 0; j < 4; j++) {
                int id = tid + j * 256;
                int r = id >> 4, c4 = (id & 15) * 4;
                float4 v = *(const float4*)(src + (size_t)r * 64 + c4);
                float vv[4] = {v.x, v.y, v.z, v.w};
#pragma unroll
                for (int e = 0; e < 4; e++) {
                    uint32_t hi = f2tf(vv[e]);
                    Kh[r * KS_STRIDE + c4 + e] = hi;
                    Kl[r * KS_STRIDE + c4 + e] = f2tf(vv[e] - __uint_as_float(hi));
                }
            }
        }
        __syncthreads();

        float hh[2][4] = {}, hl[2][4] = {}, lh[2][4] = {};
#pragma unroll
        for (int kb = 0; kb < 8; kb++) {
            uint32_t ah[2][4], al[2][4], bhf[2], blf[2];
#pragma unroll
            for (int mt = 0; mt < 2; mt++) {
                int r0 = mt * 16 + gid, c0 = kb * 8 + tg;
                ah[mt][0] = Qh[r0 * 68 + c0];       ah[mt][1] = Qh[(r0 + 8) * 68 + c0];
                ah[mt][2] = Qh[r0 * 68 + c0 + 4];   ah[mt][3] = Qh[(r0 + 8) * 68 + c0 + 4];
                al[mt][0] = Ql[r0 * 68 + c0];       al[mt][1] = Ql[(r0 + 8) * 68 + c0];
                al[mt][2] = Ql[r0 * 68 + c0 + 4];   al[mt][3] = Ql[(r0 + 8) * 68 + c0 + 4];
            }
            int br = w * 8 + gid, bc = kb * 8 + tg;
            bhf[0] = Kh[br * KS_STRIDE + bc]; bhf[1] = Kh[br * KS_STRIDE + bc + 4];
            blf[0] = Kl[br * KS_STRIDE + bc]; blf[1] = Kl[br * KS_STRIDE + bc + 4];
#pragma unroll
            for (int mt = 0; mt < 2; mt++) {
                mma8(hh[mt], ah[mt], bhf);
                mma8(hl[mt], ah[mt], blf);
                mma8(lh[mt], al[mt], bhf);
            }
        }
#pragma unroll
        for (int mt = 0; mt < 2; mt++) {
            int row = mt * 16 + gid;
            int col = mc * 64 + w * 8 + 2 * tg;
            float2 v0 = make_float2(hh[mt][0] + hl[mt][0] + lh[mt][0],
                                    hh[mt][1] + hl[mt][1] + lh[mt][1]);
            float2 v1 = make_float2(hh[mt][2] + hl[mt][2] + lh[mt][2],
                                    hh[mt][3] + hl[mt][3] + lh[mt][3]);
            *(float2*)(S + row * S_STRIDE + col)       = v0;
            *(float2*)(S + (row + 8) * S_STRIDE + col) = v1;
        }
    }
    __syncthreads();

    // ---------- epilogue: gather sp, factor, scale, mask ----------
#pragma unroll 4
    for (int it = 0; it < 32; it++) {
        const int row = it;
        const int c4  = tid * 4;
        const size_t gbase = ((size_t)(b * N_ + n0 + row)) * M_ + c4;
        float4 sc = *(float4*)(S + row * S_STRIDE + c4);
        int4   id = *(const int4*)(eidx + gbase);
        float4 fa = *(const float4*)(factor + gbase);
        const float* sprow = Sp + row * 128;
        float r0 = fa.x * (sc.x + sprow[id.x]) * 0.125f;
        float r1 = fa.y * (sc.y + sprow[id.y]) * 0.125f;
        float r2 = fa.z * (sc.z + sprow[id.z]) * 0.125f;
        float r3 = fa.w * (sc.w + sprow[id.w]) * 0.125f;
        const unsigned char* km = kmask + b * M_ + c4;
        if (km[0]) r0 = -INFINITY;
        if (km[1]) r1 = -INFINITY;
        if (km[2]) r2 = -INFINITY;
        if (km[3]) r3 = -INFINITY;
        *(float4*)(S + row * S_STRIDE + c4) = make_float4(r0, r1, r2, r3);
    }
    __syncthreads();

    // ---------- softmax (warp w owns rows w*4 .. w*4+3) ----------
    for (int rr = 0; rr < 4; rr++) {
        const int row = w * 4 + rr;
        float vals[32];
        float mx = -INFINITY;
#pragma unroll
        for (int j = 0; j < 8; j++) {
            float4 v = *(float4*)(S + row * S_STRIDE + (j * 32 + lane) * 4);
            vals[j * 4 + 0] = v.x; vals[j * 4 + 1] = v.y;
            vals[j * 4 + 2] = v.z; vals[j * 4 + 3] = v.w;
            mx = fmaxf(mx, fmaxf(fmaxf(v.x, v.y), fmaxf(v.z, v.w)));
        }
#pragma unroll
        for (int off = 16; off > 0; off >>= 1)
            mx = fmaxf(mx, __shfl_xor_sync(0xffffffffu, mx, off));
        float sum = 0.f;
#pragma unroll
        for (int i = 0; i < 32; i++) { vals[i] = __expf(vals[i] - mx); sum += vals[i]; }
#pragma unroll
        for (int off = 16; off > 0; off >>= 1)
            sum += __shfl_xor_sync(0xffffffffu, sum, off);
        const float inv = 1.0f / sum;
        const size_t abase = ((size_t)(bh * N_ + n0 + row)) * M_;
#pragma unroll
        for (int j = 0; j < 8; j++) {
            const int c4 = (j * 32 + lane) * 4;
            float p0 = vals[j * 4 + 0] * inv, p1 = vals[j * 4 + 1] * inv;
            float p2 = vals[j * 4 + 2] * inv, p3 = vals[j * 4 + 3] * inv;
            *(float4*)(attn + abase + c4) = make_float4(p0, p1, p2, p3);
            uint4 t = make_uint4(f2tf(p0), f2tf(p1), f2tf(p2), f2tf(p3));
            *(uint4*)(Su + row * S_STRIDE + c4) = t;  // tf32 bits for AV
        }
    }

    // ---------- AV: hidden(32x64) = P · V (P single tf32, V split) ----------
    float avh[2][4] = {}, avl[2][4] = {};
    for (int kc = 0; kc < 16; kc++) {
        __syncthreads();   // protect Kh/Kl reuse
        {   // stage V chunk (64 k-rows x 64 c)
            const float* src = g_v + ((size_t)bh * M_ + kc * 64) * C_;
#pragma unroll
            for (int j = 0; j < 4; j++) {
                int id = tid + j * 256;
                int r = id >> 4, c4 = (id & 15) * 4;
                float4 v = *(const float4*)(src + (size_t)r * 64 + c4);
                float vv[4] = {v.x, v.y, v.z, v.w};
#pragma unroll
                for (int e = 0; e < 4; e++) {
                    uint32_t hi = f2tf(vv[e]);
                    Kh[r * KS_STRIDE + c4 + e] = hi;
                    Kl[r * KS_STRIDE + c4 + e] = f2tf(vv[e] - __uint_as_float(hi));
                }
            }
        }
        __syncthreads();

#pragma unroll
        for (int kb = 0; kb < 8; kb++) {
            uint32_t a[2][4];
            const int cbase = kc * 64 + kb * 8;
#pragma unroll
            for (int mt = 0; mt < 2; mt++) {
                int r0 = mt * 16 + gid;
                a[mt][0] = Su[r0 * S_STRIDE + cbase + tg];
                a[mt][1] = Su[(r0 + 8) * S_STRIDE + cbase + tg];
                a[mt][2] = Su[r0 * S_STRIDE + cbase + tg + 4];
                a[mt][3] = Su[(r0 + 8) * S_STRIDE + cbase + tg + 4];
            }
            uint32_t bhf[2], blf[2];
            bhf[0] = Kh[(kb * 8 + tg) * KS_STRIDE + w * 8 + gid];
            bhf[1] = Kh[(kb * 8 + tg + 4) * KS_STRIDE + w * 8 + gid];
            blf[0] = Kl[(kb * 8 + tg) * KS_STRIDE + w * 8 + gid];
            blf[1] = Kl[(kb * 8 + tg + 4) * KS_STRIDE + w * 8 + gid];
#pragma unroll
            for (int mt = 0; mt < 2; mt++) {
                mma8(avh[mt], a[mt], bhf);
                mma8(avl[mt], a[mt], blf);
            }
        }
    }

    // store hidden: rows n0 + mt*16 + gid(+8), cols h*64 + w*8 + 2tg(+1)
#pragma unroll
    for (int mt = 0; mt < 2; mt++) {
        const int row = n0 + mt * 16 + gid;
        const int col = h * 64 + w * 8 + 2 * tg;
        float2 v0 = make_float2(avh[mt][0] + avl[mt][0], avh[mt][1] + avl[mt][1]);
        float2 v1 = make_float2(avh[mt][2] + avl[mt][2], avh[mt][3] + avl[mt][3]);
        *(float2*)(hidden + ((size_t)b * N_ + row) * D_ + col)       = v0;
        *(float2*)(hidden + ((size_t)b * N_ + row + 8) * D_ + col)   = v1;
    }
}

// ============================================================================
// Launch
// ============================================================================
extern "C" void kernel_launch(void* const* d_in, const int* in_sizes, int n_in,
                              void* d_out, int out_size)
{
    const float* input_q = (const float*)d_in[0];
    const float* input_k = (const float*)d_in[1];
    const float* input_v = (const float*)d_in[2];
    const float* Wq = (const float*)d_in[3];
    const float* bq = (const float*)d_in[4];
    const float* Wk = (const float*)d_in[5];
    const float* bk = (const float*)d_in[6];
    const float* Wv = (const float*)d_in[7];
    const float* bv = (const float*)d_in[8];
    const float* emb_table = (const float*)d_in[9];
    const float* factor = (const float*)d_in[10];
    const int* eidx = (const int*)d_in[11];
    const unsigned char* kmask = (const unsigned char*)d_in[12];

    float* hidden = (float*)d_out;                          // (B,N,D)
    float* attn   = (float*)d_out + (size_t)B_ * N_ * D_;   // (B,H,N,M)

    static int smem_set = 0;
    if (!smem_set) {
        cudaFuncSetAttribute(fused_kernel,
                             cudaFuncAttributeMaxDynamicSharedMemorySize, SMEM_BYTES);
        smem_set = 1;
    }

    proj_kernel<<<dim3((B_ * N_) / 64, D_ / 64, 3), 256>>>(
        input_q, input_k, input_v, Wq, bq, Wk, bk, Wv, bv);

    fused_kernel<<<dim3(N_ / 32, B_ * H_), 256, SMEM_BYTES>>>(
        emb_table, factor, eidx, kmask, attn, hidden);
}